// round 1
// baseline (speedup 1.0000x reference)
#include <cuda_runtime.h>
#include <math.h>

#define TILE 32
#define NTHREADS 256

// ---- packed f32x2 helpers (FFMA2 path, sm_100+) ----
__device__ __forceinline__ unsigned long long pk2(float lo, float hi) {
    unsigned long long r;
    asm("mov.b64 %0, {%1, %2};" : "=l"(r) : "f"(lo), "f"(hi));
    return r;
}
__device__ __forceinline__ void upk2(unsigned long long v, float &lo, float &hi) {
    asm("mov.b64 {%0, %1}, %2;" : "=f"(lo), "=f"(hi) : "l"(v));
}
__device__ __forceinline__ void fma2(unsigned long long &d, unsigned long long a, unsigned long long b) {
    asm("fma.rn.f32x2 %0, %1, %2, %0;" : "+l"(d) : "l"(a), "l"(b));
}
__device__ __forceinline__ float silu_f(float v) { return v / (1.0f + expf(-v)); }

// x row layout: [0:256) = xs, [256:1024) = xv interleaved (m,i): x[256 + 3m + i]
// h_s[j] = (sum_m xs[m] * w1s[m*128+j]) / 16       (j in [0,128))
// h_v[k][i] = (sum_m xv[m][i] * w1v[m*64+k]) / 16  (k in [0,64))
// out[0]   = sum_k silu(h_s[k]) * w2s[k] / 8
// out[1+i] = sum_k silu(h_s[64+k]) * h_v[k][i] * w2v[k] / 8

__global__ __launch_bounds__(NTHREADS, 1)
void fused_dipole_kernel(const float* __restrict__ x,
                         const float* __restrict__ w1s,
                         const float* __restrict__ w1v,
                         const float* __restrict__ w2s,
                         const float* __restrict__ w2v,
                         float* __restrict__ out,
                         int nrows)
{
    extern __shared__ float smem[];
    float* sx  = smem;                    // TILE * 1024
    float* shs = sx + TILE * 1024;        // TILE * 128
    float* shv = shs + TILE * 128;        // 3 * TILE * 64

    const int tid = threadIdx.x;
    const int ty  = tid >> 5;   // warp id 0..7
    const int tx  = tid & 31;   // lane
    const int r0  = blockIdx.x * TILE;

    // ---- stage x tile (coalesced float4) ----
    {
        const float4* xg  = (const float4*)x;
        float4* sx4 = (float4*)sx;
        #pragma unroll
        for (int it = 0; it < (TILE * 256) / NTHREADS; ++it) {
            int idx = tid + it * NTHREADS;          // idx = r*256 + c4
            int r = idx >> 8;
            float4 v = make_float4(0.f, 0.f, 0.f, 0.f);
            int gr = r0 + r;
            if (gr < nrows) v = xg[(long)gr * 256 + (idx & 255)];
            sx4[idx] = v;
        }
    }
    __syncthreads();

    const float inv_in = 1.0f / 16.0f;

    // each warp owns 4 rows: ty, ty+8, ty+16, ty+24 (pairs packed in f32x2)
    const float* row0 = sx + ty * 1024;
    const float* row1 = row0 + 8  * 1024;
    const float* row2 = row0 + 16 * 1024;
    const float* row3 = row0 + 24 * 1024;

    // ================= Phase S: h_s (TILE x 128), lane owns cols tx*4..tx*4+3 =================
    {
        unsigned long long accA[4], accB[4];
        #pragma unroll
        for (int j = 0; j < 4; ++j) { accA[j] = 0ull; accB[j] = 0ull; }

        const float4* wrow = (const float4*)w1s;   // [m*32 + col4]
        #pragma unroll 2
        for (int kk = 0; kk < 64; ++kk) {
            float4 a0 = ((const float4*)row0)[kk];
            float4 a1 = ((const float4*)row1)[kk];
            float4 a2 = ((const float4*)row2)[kk];
            float4 a3 = ((const float4*)row3)[kk];
            const float* f0 = (const float*)&a0;
            const float* f1 = (const float*)&a1;
            const float* f2 = (const float*)&a2;
            const float* f3 = (const float*)&a3;
            #pragma unroll
            for (int u = 0; u < 4; ++u) {
                unsigned long long A = pk2(f0[u], f1[u]);
                unsigned long long B = pk2(f2[u], f3[u]);
                float4 w = __ldg(wrow + (4 * kk + u) * 32 + tx);
                unsigned long long w0 = pk2(w.x, w.x);
                unsigned long long w1p = pk2(w.y, w.y);
                unsigned long long w2p = pk2(w.z, w.z);
                unsigned long long w3p = pk2(w.w, w.w);
                fma2(accA[0], A, w0);  fma2(accB[0], B, w0);
                fma2(accA[1], A, w1p); fma2(accB[1], B, w1p);
                fma2(accA[2], A, w2p); fma2(accB[2], B, w2p);
                fma2(accA[3], A, w3p); fma2(accB[3], B, w3p);
            }
        }
        #pragma unroll
        for (int j = 0; j < 4; ++j) {
            float lo, hi;
            upk2(accA[j], lo, hi);
            shs[(ty     ) * 128 + tx * 4 + j] = lo * inv_in;
            shs[(ty + 8 ) * 128 + tx * 4 + j] = hi * inv_in;
            upk2(accB[j], lo, hi);
            shs[(ty + 16) * 128 + tx * 4 + j] = lo * inv_in;
            shs[(ty + 24) * 128 + tx * 4 + j] = hi * inv_in;
        }
    }

    // ================= Phase V: h_v (TILE x 64 x 3), lane owns cols tx*2, tx*2+1 =================
    {
        unsigned long long accA[3][2], accB[3][2];
        #pragma unroll
        for (int i = 0; i < 3; ++i)
            #pragma unroll
            for (int c = 0; c < 2; ++c) { accA[i][c] = 0ull; accB[i][c] = 0ull; }

        for (int kk = 0; kk < 64; ++kk) {
            // 12 consecutive floats per row starting at 256 + 12*kk  (k=4kk..4kk+3, i=0..2)
            const float4* q0 = (const float4*)(row0 + 256 + 12 * kk);
            const float4* q1 = (const float4*)(row1 + 256 + 12 * kk);
            const float4* q2 = (const float4*)(row2 + 256 + 12 * kk);
            const float4* q3 = (const float4*)(row3 + 256 + 12 * kk);
            float4 p0[3] = { q0[0], q0[1], q0[2] };
            float4 p1[3] = { q1[0], q1[1], q1[2] };
            float4 p2[3] = { q2[0], q2[1], q2[2] };
            float4 p3[3] = { q3[0], q3[1], q3[2] };
            const float* g0 = (const float*)p0;
            const float* g1 = (const float*)p1;
            const float* g2 = (const float*)p2;
            const float* g3 = (const float*)p3;
            #pragma unroll
            for (int u = 0; u < 4; ++u) {
                int k = 4 * kk + u;
                float2 w = __ldg(((const float2*)(w1v + (long)k * 64)) + tx);
                unsigned long long W0 = pk2(w.x, w.x);
                unsigned long long W1 = pk2(w.y, w.y);
                #pragma unroll
                for (int i = 0; i < 3; ++i) {
                    unsigned long long A = pk2(g0[3 * u + i], g1[3 * u + i]);
                    unsigned long long B = pk2(g2[3 * u + i], g3[3 * u + i]);
                    fma2(accA[i][0], A, W0); fma2(accA[i][1], A, W1);
                    fma2(accB[i][0], B, W0); fma2(accB[i][1], B, W1);
                }
            }
        }
        #pragma unroll
        for (int i = 0; i < 3; ++i) {
            #pragma unroll
            for (int c = 0; c < 2; ++c) {
                float lo, hi;
                int col = tx * 2 + c;
                upk2(accA[i][c], lo, hi);
                shv[i * (TILE * 64) + (ty     ) * 64 + col] = lo * inv_in;
                shv[i * (TILE * 64) + (ty + 8 ) * 64 + col] = hi * inv_in;
                upk2(accB[i][c], lo, hi);
                shv[i * (TILE * 64) + (ty + 16) * 64 + col] = lo * inv_in;
                shv[i * (TILE * 64) + (ty + 24) * 64 + col] = hi * inv_in;
            }
        }
    }
    __syncthreads();

    // ================= Epilogue: 8 warps x 4 rows, lane covers k = tx, tx+32 =================
    const float inv_h = 0.125f;
    const float ws0 = __ldg(w2s + tx),      ws1 = __ldg(w2s + 32 + tx);
    const float wv0 = __ldg(w2v + tx),      wv1 = __ldg(w2v + 32 + tx);
    #pragma unroll
    for (int rr = 0; rr < 4; ++rr) {
        int r  = ty * 4 + rr;
        int gr = r0 + r;
        const float* hrow = shs + r * 128;
        float s0  = hrow[tx];        // scalars k=tx
        float s1  = hrow[32 + tx];   // scalars k=tx+32
        float gt0 = hrow[64 + tx];   // gates   k=tx
        float gt1 = hrow[96 + tx];   // gates   k=tx+32
        float os  = silu_f(s0) * ws0 + silu_f(s1) * ws1;
        float sg0 = silu_f(gt0) * wv0;
        float sg1 = silu_f(gt1) * wv1;
        float ov0 = sg0 * shv[0 * 2048 + r * 64 + tx] + sg1 * shv[0 * 2048 + r * 64 + 32 + tx];
        float ov1 = sg0 * shv[1 * 2048 + r * 64 + tx] + sg1 * shv[1 * 2048 + r * 64 + 32 + tx];
        float ov2 = sg0 * shv[2 * 2048 + r * 64 + tx] + sg1 * shv[2 * 2048 + r * 64 + 32 + tx];
        #pragma unroll
        for (int off = 16; off > 0; off >>= 1) {
            os  += __shfl_xor_sync(0xffffffffu, os,  off);
            ov0 += __shfl_xor_sync(0xffffffffu, ov0, off);
            ov1 += __shfl_xor_sync(0xffffffffu, ov1, off);
            ov2 += __shfl_xor_sync(0xffffffffu, ov2, off);
        }
        if (tx == 0 && gr < nrows) {
            float4 o = make_float4(os * inv_h, ov0 * inv_h, ov1 * inv_h, ov2 * inv_h);
            ((float4*)out)[gr] = o;
        }
    }
}

extern "C" void kernel_launch(void* const* d_in, const int* in_sizes, int n_in,
                              void* d_out, int out_size)
{
    const float* x   = (const float*)d_in[0];
    const float* w1s = (const float*)d_in[1];
    const float* w1v = (const float*)d_in[2];
    const float* w2s = (const float*)d_in[3];
    const float* w2v = (const float*)d_in[4];
    float* out = (float*)d_out;

    int nrows  = in_sizes[0] / 1024;
    int blocks = (nrows + TILE - 1) / TILE;
    size_t smem_bytes = (size_t)(TILE * 1024 + TILE * 128 + 3 * TILE * 64) * sizeof(float); // 172032

    cudaFuncSetAttribute(fused_dipole_kernel,
                         cudaFuncAttributeMaxDynamicSharedMemorySize, (int)smem_bytes);
    fused_dipole_kernel<<<blocks, NTHREADS, smem_bytes>>>(x, w1s, w1v, w2s, w2v, out, nrows);
}